// round 10
// baseline (speedup 1.0000x reference)
#include <cuda_runtime.h>

// Row-wise softmax (no max subtraction): y = exp(x) / sum(exp(x), axis=-1)
// x: (16384, 4096) fp32.
// 1 CTA per row, 512 threads. Each thread handles 8 consecutive floats via
// ONE 256-bit load and ONE 256-bit store (Blackwell LDG.E.256/STG.E.256),
// halving LSU dispatches vs the 2x float4 version. Evict-first (.cs) policy
// on both streams (single-touch data).

#define COLS 4096
#define THREADS 512   // 512 * 8 = 4096 floats per row

struct f8 { float v[8]; };

__device__ __forceinline__ f8 ldcs8(const float* p) {
    f8 r;
    asm volatile(
        "ld.global.cs.v8.f32 {%0,%1,%2,%3,%4,%5,%6,%7}, [%8];"
        : "=f"(r.v[0]), "=f"(r.v[1]), "=f"(r.v[2]), "=f"(r.v[3]),
          "=f"(r.v[4]), "=f"(r.v[5]), "=f"(r.v[6]), "=f"(r.v[7])
        : "l"(p));
    return r;
}

__device__ __forceinline__ void stcs8(float* p, const f8& r) {
    asm volatile(
        "st.global.cs.v8.f32 [%0], {%1,%2,%3,%4,%5,%6,%7,%8};"
        :: "l"(p),
           "f"(r.v[0]), "f"(r.v[1]), "f"(r.v[2]), "f"(r.v[3]),
           "f"(r.v[4]), "f"(r.v[5]), "f"(r.v[6]), "f"(r.v[7]));
}

__global__ __launch_bounds__(THREADS, 4)
void softmax_row_v8_kernel(const float* __restrict__ x,
                           float* __restrict__ y) {
    const int row = blockIdx.x;
    const size_t base = (size_t)row * COLS + (size_t)threadIdx.x * 8;
    const int tid = threadIdx.x;

    // Single 256-bit load, exp in registers.
    f8 t = ldcs8(x + base);
    float local = 0.0f;
#pragma unroll
    for (int i = 0; i < 8; ++i) {
        t.v[i] = __expf(t.v[i]);
        local += t.v[i];
    }

    // Block reduction: warp shuffle then 16 warp sums via smem broadcast.
    __shared__ float warp_sums[THREADS / 32];
#pragma unroll
    for (int o = 16; o > 0; o >>= 1)
        local += __shfl_xor_sync(0xFFFFFFFFu, local, o);
    if ((tid & 31) == 0)
        warp_sums[tid >> 5] = local;
    __syncthreads();

    float total = 0.0f;
#pragma unroll
    for (int w = 0; w < THREADS / 32; ++w)
        total += warp_sums[w];  // broadcast LDS, conflict-free

    const float inv = 1.0f / total;

#pragma unroll
    for (int i = 0; i < 8; ++i)
        t.v[i] *= inv;

    // Single 256-bit store.
    stcs8(y + base, t);
}

extern "C" void kernel_launch(void* const* d_in, const int* in_sizes, int n_in,
                              void* d_out, int out_size) {
    const float* x = (const float*)d_in[0];
    float* y = (float*)d_out;
    const int rows = in_sizes[0] / COLS;  // 16384
    softmax_row_v8_kernel<<<rows, THREADS>>>(x, y);
}

// round 11
// speedup vs baseline: 1.0143x; 1.0143x over previous
#include <cuda_runtime.h>

// FINAL KERNEL (best measured: 80.58us wall, ~6.4TB/s HBM, 81% of spec).
// Row-wise softmax (no max subtraction, matching reference):
//   y = exp(x) / sum(exp(x), axis=-1)
// x: (16384, 4096) fp32.
//
// Design (each choice validated by measurement against alternatives):
//  - 1 CTA per row, 512 threads, 8 floats/thread as 2x float4 in registers
//    (beat 256t/VPT4, 128t/VPT8, 1024t/VPT1, and 512t/v8 variants).
//  - Exactly 1 read + 1 write per element = 512 MiB, the traffic minimum.
//  - Front-batched LDG.128 pair (MLP_p1=2): small per-CTA bursts keep the
//    per-SM L1tex queue smooth across 4 resident CTAs.
//  - Evict-first (.cs) stores: output is never re-read; keeps L2 staging
//    for the read stream (measured +0.4us vs default stores).
//  - Plain loads: .cs on loads measured neutral; default is simplest.
//  - Block reduce: 5 warp shuffles + 16-entry smem broadcast, one barrier.

#define COLS 4096
#define THREADS 512
#define VPT 2   // 2 x float4 = 8 floats; 512*8 = 4096

__device__ __forceinline__ void stcs4(float4* p, float4 v) {
    asm volatile("st.global.cs.v4.f32 [%0], {%1,%2,%3,%4};"
                 :: "l"(p), "f"(v.x), "f"(v.y), "f"(v.z), "f"(v.w));
}

__global__ __launch_bounds__(THREADS, 4)
void softmax_row512_kernel(const float4* __restrict__ x,
                           float4* __restrict__ y) {
    const int row = blockIdx.x;
    const size_t base = (size_t)row * (COLS / 4);
    const float4* xr = x + base;
    float4* yr = y + base;
    const int tid = threadIdx.x;

    float4 v[VPT];
    float local = 0.0f;

    // Front-batched vector loads (MLP_p1 = 2), exp on the fly.
#pragma unroll
    for (int i = 0; i < VPT; ++i) {
        float4 t = xr[tid + i * THREADS];
        t.x = __expf(t.x);
        t.y = __expf(t.y);
        t.z = __expf(t.z);
        t.w = __expf(t.w);
        local += (t.x + t.y) + (t.z + t.w);
        v[i] = t;
    }

    // Block reduction: warp shuffle then 16 warp sums via smem broadcast.
    __shared__ float warp_sums[THREADS / 32];
#pragma unroll
    for (int o = 16; o > 0; o >>= 1)
        local += __shfl_xor_sync(0xFFFFFFFFu, local, o);
    if ((tid & 31) == 0)
        warp_sums[tid >> 5] = local;
    __syncthreads();

    float total = 0.0f;
#pragma unroll
    for (int w = 0; w < THREADS / 32; ++w)
        total += warp_sums[w];  // broadcast LDS, conflict-free

    const float inv = 1.0f / total;

#pragma unroll
    for (int i = 0; i < VPT; ++i) {
        float4 t = v[i];
        t.x *= inv;
        t.y *= inv;
        t.z *= inv;
        t.w *= inv;
        stcs4(yr + tid + i * THREADS, t);
    }
}

extern "C" void kernel_launch(void* const* d_in, const int* in_sizes, int n_in,
                              void* d_out, int out_size) {
    const float4* x = (const float4*)d_in[0];
    float4* y = (float4*)d_out;
    const int rows = in_sizes[0] / COLS;  // 16384
    softmax_row512_kernel<<<rows, THREADS>>>(x, y);
}